// round 1
// baseline (speedup 1.0000x reference)
#include <cuda_runtime.h>

// Modified Bessel K1(x), Abramowitz & Stegun 9.8.7 / 9.8.8, matching the
// JAX fp32 reference. Branchless: both branches evaluated, select at end.
// For x>2 the "small" branch is discarded, so it is safe to evaluate it
// with x directly (no clamp to 2) — everything is finite on (0.1, 10.1].
// This lets a single rcp(x) serve both 1/xs and w = 2/x (4 MUFU/elt total).
__device__ __forceinline__ float k1f(float x) {
    const float r = __frcp_rn(x);

    // ---- small branch (x <= 2): log(x/2)*I1_small(x) + (1/x)*P(t) ----
    float h = x * 0.5f;
    float t = h * h;                      // (x/2)^2
    float xu = x * 0.26666667f;           // x / 3.75
    float u = xu * xu;                    // (x/3.75)^2

    // I1_small poly in u (A&S 9.8.3), Horner highest-first
    float p1 = 0.00032411f;
    p1 = fmaf(p1, u, 0.00301532f);
    p1 = fmaf(p1, u, 0.02658733f);
    p1 = fmaf(p1, u, 0.15084934f);
    p1 = fmaf(p1, u, 0.51498869f);
    p1 = fmaf(p1, u, 0.87890594f);
    p1 = fmaf(p1, u, 0.5f);
    float i1 = x * p1;

    // K1 small poly in t (A&S 9.8.7)
    float p2 = -0.00004686f;
    p2 = fmaf(p2, t, -0.00110404f);
    p2 = fmaf(p2, t, -0.01919402f);
    p2 = fmaf(p2, t, -0.18156897f);
    p2 = fmaf(p2, t, -0.67278579f);
    p2 = fmaf(p2, t, 0.15443144f);
    p2 = fmaf(p2, t, 1.0f);

    float lg = __logf(h);                 // log(x/2)
    float small = fmaf(lg, i1, r * p2);

    // ---- large branch (x > 2): exp(-x)/sqrt(x) * Q(2/x) ----
    float w = 2.0f * r;
    float p3 = -0.00068245f;
    p3 = fmaf(p3, w, 0.00325614f);
    p3 = fmaf(p3, w, -0.00780353f);
    p3 = fmaf(p3, w, 0.01504268f);
    p3 = fmaf(p3, w, -0.03655620f);
    p3 = fmaf(p3, w, 0.23498619f);
    p3 = fmaf(p3, w, 1.25331414f);
    float large = __expf(-x) * rsqrtf(x) * p3;

    return (x <= 2.0f) ? small : large;
}

__global__ void __launch_bounds__(256) k1_kernel_v4(const float4* __restrict__ in,
                                                    float4* __restrict__ out,
                                                    int n4) {
    int i = blockIdx.x * blockDim.x + threadIdx.x;
    if (i < n4) {
        float4 v = in[i];
        float4 o;
        o.x = k1f(v.x);
        o.y = k1f(v.y);
        o.z = k1f(v.z);
        o.w = k1f(v.w);
        out[i] = o;
    }
}

// Scalar tail fallback (not needed for 8192*8192, but safe)
__global__ void k1_kernel_tail(const float* __restrict__ in,
                               float* __restrict__ out,
                               int start, int n) {
    int i = start + blockIdx.x * blockDim.x + threadIdx.x;
    if (i < n) out[i] = k1f(in[i]);
}

extern "C" void kernel_launch(void* const* d_in, const int* in_sizes, int n_in,
                              void* d_out, int out_size) {
    const float* x = (const float*)d_in[0];
    float* y = (float*)d_out;
    int n = in_sizes[0];

    int n4 = n / 4;
    if (n4 > 0) {
        int threads = 256;
        int blocks = (n4 + threads - 1) / threads;
        k1_kernel_v4<<<blocks, threads>>>((const float4*)x, (float4*)y, n4);
    }
    int rem = n - n4 * 4;
    if (rem > 0) {
        k1_kernel_tail<<<1, 256>>>(x, y, n4 * 4, n);
    }
}

// round 2
// speedup vs baseline: 1.4042x; 1.4042x over previous
#include <cuda_runtime.h>

// Modified Bessel K1(x) on (0.1, 10.1], matching the JAX fp32 A&S reference.
//
// Rewritten with packed f32x2 math (Blackwell FFMA2 path): all polynomial
// work processes 2 elements per instruction. Constant foldings:
//   small(x) = ln(x/2)*I1(x) + (1/x)*P2((x/2)^2)
//            = (lg2(x)-1) * x * P1ln(x^2) + r * P2s(x^2)
//     where P1ln coeffs absorb ln2 and 3.75^-2k, P2s coeffs absorb 4^-k
//   large(x) = exp(-x)/sqrt(x) * P3(2/x)
//            = ex2(-log2e*x - 0.5*lg2(x)) * P3r(r)
//     where P3r coeffs absorb 2^k, r = rcp(x)
// MUFU per element: rcp, lg2, ex2 (3 total; rsqrt eliminated via lg2 reuse).

typedef unsigned long long ull;

__device__ __forceinline__ ull f2(float lo, float hi) {
    ull d; asm("mov.b64 %0,{%1,%2};" : "=l"(d) : "f"(lo), "f"(hi)); return d;
}
__device__ __forceinline__ ull dup(float c) { return f2(c, c); }
__device__ __forceinline__ void unpack2(ull v, float& lo, float& hi) {
    asm("mov.b64 {%0,%1},%2;" : "=f"(lo), "=f"(hi) : "l"(v));
}
__device__ __forceinline__ ull ffma2(ull a, ull b, ull c) {
    ull d; asm("fma.rn.f32x2 %0,%1,%2,%3;" : "=l"(d) : "l"(a), "l"(b), "l"(c)); return d;
}
__device__ __forceinline__ ull fmul2(ull a, ull b) {
    ull d; asm("mul.rn.f32x2 %0,%1,%2;" : "=l"(d) : "l"(a), "l"(b)); return d;
}
__device__ __forceinline__ ull fadd2(ull a, ull b) {
    ull d; asm("add.rn.f32x2 %0,%1,%2;" : "=l"(d) : "l"(a), "l"(b)); return d;
}
__device__ __forceinline__ float rcpa(float x) {
    float y; asm("rcp.approx.f32 %0,%1;" : "=f"(y) : "f"(x)); return y;
}
__device__ __forceinline__ float lg2a(float x) {
    float y; asm("lg2.approx.f32 %0,%1;" : "=f"(y) : "f"(x)); return y;
}
__device__ __forceinline__ float ex2a(float x) {
    float y; asm("ex2.approx.f32 %0,%1;" : "=f"(y) : "f"(x)); return y;
}

__device__ __forceinline__ void k1_pair(float x0, float x1, float& y0, float& y1) {
    const ull x = f2(x0, x1);
    // Scalar MUFUs
    const ull r = f2(rcpa(x0), rcpa(x1));
    const ull L = f2(lg2a(x0), lg2a(x1));

    const ull s = fmul2(x, x);

    // P1ln(s): ln2 * I1_small poly, refolded to s = x^2  (A&S 9.8.3)
    ull p1 = dup(2.9049205e-11f);
    p1 = ffma2(p1, s, dup(3.8004737e-9f));
    p1 = ffma2(p1, s, dup(4.7126267e-7f));
    p1 = ffma2(p1, s, dup(3.7598484e-5f));
    p1 = ffma2(p1, s, dup(1.8051333e-3f));
    p1 = ffma2(p1, s, dup(4.3321636e-2f));
    p1 = ffma2(p1, s, dup(0.34657359f));

    // P2s(s): K1 small poly, refolded to s = x^2  (A&S 9.8.7)
    ull p2 = dup(-1.1440430e-8f);
    p2 = ffma2(p2, s, dup(-1.0781641e-6f));
    p2 = ffma2(p2, s, dup(-7.4976641e-5f));
    p2 = ffma2(p2, s, dup(-2.8370152e-3f));
    p2 = ffma2(p2, s, dup(-4.2049112e-2f));
    p2 = ffma2(p2, s, dup(3.8607860e-2f));
    p2 = ffma2(p2, s, dup(1.0f));

    // P3r(r): K1 large poly in w=2/x, refolded to r = 1/x  (A&S 9.8.8)
    ull p3 = dup(-0.04367680f);
    p3 = ffma2(p3, r, dup(0.10419648f));
    p3 = ffma2(p3, r, dup(-0.12485648f));
    p3 = ffma2(p3, r, dup(0.12034144f));
    p3 = ffma2(p3, r, dup(-0.14622480f));
    p3 = ffma2(p3, r, dup(0.46997238f));
    p3 = ffma2(p3, r, dup(1.25331414f));

    // small = (L - 1) * (x * P1ln) + r * P2s
    const ull xp1 = fmul2(x, p1);
    const ull Lm1 = fadd2(L, dup(-1.0f));
    const ull small2 = ffma2(Lm1, xp1, fmul2(r, p2));

    // large = ex2(-0.5*L - log2e*x) * P3r
    const ull earg = ffma2(dup(-0.5f), L, fmul2(dup(-1.44269504f), x));
    float ea0, ea1; unpack2(earg, ea0, ea1);
    const ull E = f2(ex2a(ea0), ex2a(ea1));
    const ull large2 = fmul2(E, p3);

    float s0, s1, l0, l1;
    unpack2(small2, s0, s1);
    unpack2(large2, l0, l1);
    y0 = (x0 <= 2.0f) ? s0 : l0;
    y1 = (x1 <= 2.0f) ? s1 : l1;
}

static constexpr int TPB = 256;
static constexpr int V4_PER_THREAD = 4;

__global__ void __launch_bounds__(TPB) k1_kernel_v2(const float4* __restrict__ in,
                                                    float4* __restrict__ out,
                                                    int n4) {
    int base = blockIdx.x * (TPB * V4_PER_THREAD) + threadIdx.x;
#pragma unroll
    for (int k = 0; k < V4_PER_THREAD; k++) {
        int i = base + k * TPB;
        if (i < n4) {
            float4 v = in[i];
            float4 o;
            k1_pair(v.x, v.y, o.x, o.y);
            k1_pair(v.z, v.w, o.z, o.w);
            out[i] = o;
        }
    }
}

// Scalar tail (n not divisible by 4) — not hit for 8192x8192 but kept safe.
__device__ __forceinline__ float k1_scalar(float x) {
    float r = rcpa(x), L = lg2a(x);
    float s = x * x;
    float p1 = 2.9049205e-11f;
    p1 = fmaf(p1, s, 3.8004737e-9f);
    p1 = fmaf(p1, s, 4.7126267e-7f);
    p1 = fmaf(p1, s, 3.7598484e-5f);
    p1 = fmaf(p1, s, 1.8051333e-3f);
    p1 = fmaf(p1, s, 4.3321636e-2f);
    p1 = fmaf(p1, s, 0.34657359f);
    float p2 = -1.1440430e-8f;
    p2 = fmaf(p2, s, -1.0781641e-6f);
    p2 = fmaf(p2, s, -7.4976641e-5f);
    p2 = fmaf(p2, s, -2.8370152e-3f);
    p2 = fmaf(p2, s, -4.2049112e-2f);
    p2 = fmaf(p2, s, 3.8607860e-2f);
    p2 = fmaf(p2, s, 1.0f);
    float p3 = -0.04367680f;
    p3 = fmaf(p3, r, 0.10419648f);
    p3 = fmaf(p3, r, -0.12485648f);
    p3 = fmaf(p3, r, 0.12034144f);
    p3 = fmaf(p3, r, -0.14622480f);
    p3 = fmaf(p3, r, 0.46997238f);
    p3 = fmaf(p3, r, 1.25331414f);
    float small = fmaf((L - 1.0f) , x * p1, r * p2);
    float large = ex2a(fmaf(-0.5f, L, -1.44269504f * x)) * p3;
    return (x <= 2.0f) ? small : large;
}

__global__ void k1_kernel_tail(const float* __restrict__ in,
                               float* __restrict__ out,
                               int start, int n) {
    int i = start + blockIdx.x * blockDim.x + threadIdx.x;
    if (i < n) out[i] = k1_scalar(in[i]);
}

extern "C" void kernel_launch(void* const* d_in, const int* in_sizes, int n_in,
                              void* d_out, int out_size) {
    const float* x = (const float*)d_in[0];
    float* y = (float*)d_out;
    int n = in_sizes[0];

    int n4 = n / 4;
    if (n4 > 0) {
        int per_block = TPB * V4_PER_THREAD;
        int blocks = (n4 + per_block - 1) / per_block;
        k1_kernel_v2<<<blocks, TPB>>>((const float4*)x, (float4*)y, n4);
    }
    int rem = n - n4 * 4;
    if (rem > 0) {
        k1_kernel_tail<<<1, 256>>>(x, y, n4 * 4, n);
    }
}

// round 3
// speedup vs baseline: 1.4310x; 1.0191x over previous
#include <cuda_runtime.h>

// Modified Bessel K1(x) on (0.1, 10.1], matching the JAX fp32 A&S reference
// to ~3e-4 (threshold 1e-3). Packed f32x2 math throughout; polynomials
// Chebyshev-economized against the 1e-3 budget:
//   small(x) = (lg2(x)-1) * x * P1(x^2) + rcp(x) * P2(x^2)      [x <= 2]
//   large(x) = ex2(-0.5*lg2(x) - log2e*x) * P3(rcp(x))          [x > 2]
// 3 MUFU/elt (rcp, lg2, ex2), 19 packed fma-class ops per pair.

typedef unsigned long long ull;

__device__ __forceinline__ ull f2(float lo, float hi) {
    ull d; asm("mov.b64 %0,{%1,%2};" : "=l"(d) : "f"(lo), "f"(hi)); return d;
}
__device__ __forceinline__ ull dup(float c) { return f2(c, c); }
__device__ __forceinline__ void unpack2(ull v, float& lo, float& hi) {
    asm("mov.b64 {%0,%1},%2;" : "=f"(lo), "=f"(hi) : "l"(v));
}
__device__ __forceinline__ ull ffma2(ull a, ull b, ull c) {
    ull d; asm("fma.rn.f32x2 %0,%1,%2,%3;" : "=l"(d) : "l"(a), "l"(b), "l"(c)); return d;
}
__device__ __forceinline__ ull fmul2(ull a, ull b) {
    ull d; asm("mul.rn.f32x2 %0,%1,%2;" : "=l"(d) : "l"(a), "l"(b)); return d;
}
__device__ __forceinline__ ull fadd2(ull a, ull b) {
    ull d; asm("add.rn.f32x2 %0,%1,%2;" : "=l"(d) : "l"(a), "l"(b)); return d;
}
__device__ __forceinline__ float rcpa(float x) {
    float y; asm("rcp.approx.f32 %0,%1;" : "=f"(y) : "f"(x)); return y;
}
__device__ __forceinline__ float lg2a(float x) {
    float y; asm("lg2.approx.f32 %0,%1;" : "=f"(y) : "f"(x)); return y;
}
__device__ __forceinline__ float ex2a(float x) {
    float y; asm("ex2.approx.f32 %0,%1;" : "=f"(y) : "f"(x)); return y;
}
__device__ __forceinline__ void ldg_cs2(const void* p, ull& a, ull& b) {
    asm("ld.global.cs.v2.u64 {%0,%1},[%2];" : "=l"(a), "=l"(b) : "l"(p));
}
__device__ __forceinline__ void stg_cs2(void* p, ull a, ull b) {
    asm("st.global.cs.v2.u64 [%0],{%1,%2};" :: "l"(p), "l"(a), "l"(b) : "memory");
}

__device__ __forceinline__ ull k1_pair2(ull x) {
    float x0, x1; unpack2(x, x0, x1);
    const ull r = f2(rcpa(x0), rcpa(x1));
    const ull L = f2(lg2a(x0), lg2a(x1));
    const ull s = fmul2(x, x);

    // P1(s): ln2 * I1_small refolded to s = x^2, economized to degree 3
    ull p1 = dup(3.9483535e-5f);
    p1 = ffma2(p1, s, dup(1.8039269e-3f));
    p1 = ffma2(p1, s, dup(4.3321636e-2f));
    p1 = ffma2(p1, s, dup(0.34657359f));

    // P2(s): K1 small poly refolded to s = x^2, economized to degree 5
    ull p2 = dup(-1.1239261e-6f);
    p2 = ffma2(p2, s, dup(-7.4947353e-5f));
    p2 = ffma2(p2, s, dup(-2.8370152e-3f));
    p2 = ffma2(p2, s, dup(-4.2049112e-2f));
    p2 = ffma2(p2, s, dup(3.8607860e-2f));
    p2 = ffma2(p2, s, dup(1.0f));

    // P3(r): K1 large poly refolded to r = 1/x, economized to degree 4
    ull p3 = dup(-0.07165131f);
    p3 = ffma2(p3, r, dup(0.11351885f));
    p3 = ffma2(p3, r, dup(-0.14622480f));
    p3 = ffma2(p3, r, dup(0.46997238f));
    p3 = ffma2(p3, r, dup(1.25331414f));

    // small = (L - 1) * (x * P1) + r * P2
    const ull xp1 = fmul2(x, p1);
    const ull Lm1 = fadd2(L, dup(-1.0f));
    const ull small2 = ffma2(Lm1, xp1, fmul2(r, p2));

    // large = ex2(-0.5*L - log2e*x) * P3
    const ull earg = ffma2(L, dup(-0.5f), fmul2(x, dup(-1.44269504f)));
    float e0, e1; unpack2(earg, e0, e1);
    const ull large2 = fmul2(f2(ex2a(e0), ex2a(e1)), p3);

    float s0, s1, l0, l1;
    unpack2(small2, s0, s1);
    unpack2(large2, l0, l1);
    float y0 = (x0 <= 2.0f) ? s0 : l0;
    float y1 = (x1 <= 2.0f) ? s1 : l1;
    return f2(y0, y1);
}

static constexpr int TPB = 256;
static constexpr int V4 = 4;  // float4s per thread

// Full-tile main kernel: no bounds checks, loads front-batched (MLP=4).
__global__ void __launch_bounds__(TPB) k1_main(const float4* __restrict__ in,
                                               float4* __restrict__ out) {
    int i = blockIdx.x * (TPB * V4) + threadIdx.x;
    ull a[V4], b[V4];
#pragma unroll
    for (int k = 0; k < V4; k++)
        ldg_cs2(&in[i + k * TPB], a[k], b[k]);
    ull ra[V4], rb[V4];
#pragma unroll
    for (int k = 0; k < V4; k++) {
        ra[k] = k1_pair2(a[k]);
        rb[k] = k1_pair2(b[k]);
    }
#pragma unroll
    for (int k = 0; k < V4; k++)
        stg_cs2(&out[i + k * TPB], ra[k], rb[k]);
}

// Generic scalar tail for leftover elements (unused for 8192x8192).
__device__ __forceinline__ float k1_scalar(float x) {
    float r = rcpa(x), L = lg2a(x);
    float s = x * x;
    float p1 = 3.9483535e-5f;
    p1 = fmaf(p1, s, 1.8039269e-3f);
    p1 = fmaf(p1, s, 4.3321636e-2f);
    p1 = fmaf(p1, s, 0.34657359f);
    float p2 = -1.1239261e-6f;
    p2 = fmaf(p2, s, -7.4947353e-5f);
    p2 = fmaf(p2, s, -2.8370152e-3f);
    p2 = fmaf(p2, s, -4.2049112e-2f);
    p2 = fmaf(p2, s, 3.8607860e-2f);
    p2 = fmaf(p2, s, 1.0f);
    float p3 = -0.07165131f;
    p3 = fmaf(p3, r, 0.11351885f);
    p3 = fmaf(p3, r, -0.14622480f);
    p3 = fmaf(p3, r, 0.46997238f);
    p3 = fmaf(p3, r, 1.25331414f);
    float small = fmaf(L - 1.0f, x * p1, r * p2);
    float large = ex2a(fmaf(-0.5f, L, -1.44269504f * x)) * p3;
    return (x <= 2.0f) ? small : large;
}

__global__ void k1_tail(const float* __restrict__ in, float* __restrict__ out,
                        int start, int n) {
    int i = start + blockIdx.x * blockDim.x + threadIdx.x;
    if (i < n) out[i] = k1_scalar(in[i]);
}

extern "C" void kernel_launch(void* const* d_in, const int* in_sizes, int n_in,
                              void* d_out, int out_size) {
    const float* x = (const float*)d_in[0];
    float* y = (float*)d_out;
    int n = in_sizes[0];

    int elems_per_block = TPB * V4 * 4;                  // 4096 elements
    int full_blocks = n / elems_per_block;
    if (full_blocks > 0) {
        k1_main<<<full_blocks, TPB>>>((const float4*)x, (float4*)y);
    }
    int done = full_blocks * elems_per_block;
    int rem = n - done;
    if (rem > 0) {
        int blocks = (rem + 255) / 256;
        k1_tail<<<blocks, 256>>>(x, y, done, n);
    }
}

// round 4
// speedup vs baseline: 1.5996x; 1.1178x over previous
#include <cuda_runtime.h>

// Modified Bessel K1(x) on (0.1, 10.1], matching the JAX fp32 A&S reference
// to ~1e-6..3e-4 (threshold 1e-3). Packed f32x2 math; polynomials
// Chebyshev-economized:
//   small(x) = (lg2(x)-1) * x * P1(x^2) + rcp(x) * P2(x^2)      [x <= 2]
//   large(x) = ex2(-0.5*lg2(x) - log2e*x) * P3(rcp(x))          [x > 2]
// 3 MUFU/elt. R4: V=2 float4/thread + interleaved store to cut registers
// and restore occupancy (R3 was latency-bound at occ=63%).

typedef unsigned long long ull;

__device__ __forceinline__ ull f2(float lo, float hi) {
    ull d; asm("mov.b64 %0,{%1,%2};" : "=l"(d) : "f"(lo), "f"(hi)); return d;
}
__device__ __forceinline__ ull dup(float c) { return f2(c, c); }
__device__ __forceinline__ void unpack2(ull v, float& lo, float& hi) {
    asm("mov.b64 {%0,%1},%2;" : "=f"(lo), "=f"(hi) : "l"(v));
}
__device__ __forceinline__ ull ffma2(ull a, ull b, ull c) {
    ull d; asm("fma.rn.f32x2 %0,%1,%2,%3;" : "=l"(d) : "l"(a), "l"(b), "l"(c)); return d;
}
__device__ __forceinline__ ull fmul2(ull a, ull b) {
    ull d; asm("mul.rn.f32x2 %0,%1,%2;" : "=l"(d) : "l"(a), "l"(b)); return d;
}
__device__ __forceinline__ ull fadd2(ull a, ull b) {
    ull d; asm("add.rn.f32x2 %0,%1,%2;" : "=l"(d) : "l"(a), "l"(b)); return d;
}
__device__ __forceinline__ float rcpa(float x) {
    float y; asm("rcp.approx.f32 %0,%1;" : "=f"(y) : "f"(x)); return y;
}
__device__ __forceinline__ float lg2a(float x) {
    float y; asm("lg2.approx.f32 %0,%1;" : "=f"(y) : "f"(x)); return y;
}
__device__ __forceinline__ float ex2a(float x) {
    float y; asm("ex2.approx.f32 %0,%1;" : "=f"(y) : "f"(x)); return y;
}
__device__ __forceinline__ void ldg_cs2(const void* p, ull& a, ull& b) {
    asm("ld.global.cs.v2.u64 {%0,%1},[%2];" : "=l"(a), "=l"(b) : "l"(p));
}
__device__ __forceinline__ void stg_cs2(void* p, ull a, ull b) {
    asm("st.global.cs.v2.u64 [%0],{%1,%2};" :: "l"(p), "l"(a), "l"(b) : "memory");
}

__device__ __forceinline__ ull k1_pair2(ull x) {
    float x0, x1; unpack2(x, x0, x1);
    const ull r = f2(rcpa(x0), rcpa(x1));
    const ull L = f2(lg2a(x0), lg2a(x1));
    const ull s = fmul2(x, x);

    // P1(s): ln2 * I1_small refolded to s = x^2, economized to degree 3
    ull p1 = dup(3.9483535e-5f);
    p1 = ffma2(p1, s, dup(1.8039269e-3f));
    p1 = ffma2(p1, s, dup(4.3321636e-2f));
    p1 = ffma2(p1, s, dup(0.34657359f));

    // P2(s): K1 small poly refolded to s = x^2, economized to degree 5
    ull p2 = dup(-1.1239261e-6f);
    p2 = ffma2(p2, s, dup(-7.4947353e-5f));
    p2 = ffma2(p2, s, dup(-2.8370152e-3f));
    p2 = ffma2(p2, s, dup(-4.2049112e-2f));
    p2 = ffma2(p2, s, dup(3.8607860e-2f));
    p2 = ffma2(p2, s, dup(1.0f));

    // P3(r): K1 large poly refolded to r = 1/x, economized to degree 4
    ull p3 = dup(-0.07165131f);
    p3 = ffma2(p3, r, dup(0.11351885f));
    p3 = ffma2(p3, r, dup(-0.14622480f));
    p3 = ffma2(p3, r, dup(0.46997238f));
    p3 = ffma2(p3, r, dup(1.25331414f));

    // small = (L - 1) * (x * P1) + r * P2
    const ull xp1 = fmul2(x, p1);
    const ull Lm1 = fadd2(L, dup(-1.0f));
    const ull small2 = ffma2(Lm1, xp1, fmul2(r, p2));

    // large = ex2(-0.5*L - log2e*x) * P3
    const ull earg = ffma2(L, dup(-0.5f), fmul2(x, dup(-1.44269504f)));
    float e0, e1; unpack2(earg, e0, e1);
    const ull large2 = fmul2(f2(ex2a(e0), ex2a(e1)), p3);

    float s0, s1, l0, l1;
    unpack2(small2, s0, s1);
    unpack2(large2, l0, l1);
    float y0 = (x0 <= 2.0f) ? s0 : l0;
    float y1 = (x1 <= 2.0f) ? s1 : l1;
    return f2(y0, y1);
}

static constexpr int TPB = 256;
static constexpr int V = 2;  // float4s per thread

// Full-tile main kernel: loads front-batched (MLP=2), compute->store
// interleaved per tile to minimize live registers (occupancy first).
__global__ void __launch_bounds__(TPB) k1_main(const float4* __restrict__ in,
                                               float4* __restrict__ out) {
    int i = blockIdx.x * (TPB * V) + threadIdx.x;
    ull a0, b0, a1, b1;
    ldg_cs2(&in[i], a0, b0);
    ldg_cs2(&in[i + TPB], a1, b1);
    stg_cs2(&out[i], k1_pair2(a0), k1_pair2(b0));
    stg_cs2(&out[i + TPB], k1_pair2(a1), k1_pair2(b1));
}

// Generic scalar tail for leftover elements (unused for 8192x8192).
__device__ __forceinline__ float k1_scalar(float x) {
    float r = rcpa(x), L = lg2a(x);
    float s = x * x;
    float p1 = 3.9483535e-5f;
    p1 = fmaf(p1, s, 1.8039269e-3f);
    p1 = fmaf(p1, s, 4.3321636e-2f);
    p1 = fmaf(p1, s, 0.34657359f);
    float p2 = -1.1239261e-6f;
    p2 = fmaf(p2, s, -7.4947353e-5f);
    p2 = fmaf(p2, s, -2.8370152e-3f);
    p2 = fmaf(p2, s, -4.2049112e-2f);
    p2 = fmaf(p2, s, 3.8607860e-2f);
    p2 = fmaf(p2, s, 1.0f);
    float p3 = -0.07165131f;
    p3 = fmaf(p3, r, 0.11351885f);
    p3 = fmaf(p3, r, -0.14622480f);
    p3 = fmaf(p3, r, 0.46997238f);
    p3 = fmaf(p3, r, 1.25331414f);
    float small = fmaf(L - 1.0f, x * p1, r * p2);
    float large = ex2a(fmaf(-0.5f, L, -1.44269504f * x)) * p3;
    return (x <= 2.0f) ? small : large;
}

__global__ void k1_tail(const float* __restrict__ in, float* __restrict__ out,
                        int start, int n) {
    int i = start + blockIdx.x * blockDim.x + threadIdx.x;
    if (i < n) out[i] = k1_scalar(in[i]);
}

extern "C" void kernel_launch(void* const* d_in, const int* in_sizes, int n_in,
                              void* d_out, int out_size) {
    const float* x = (const float*)d_in[0];
    float* y = (float*)d_out;
    int n = in_sizes[0];

    int elems_per_block = TPB * V * 4;                   // 2048 elements
    int full_blocks = n / elems_per_block;
    if (full_blocks > 0) {
        k1_main<<<full_blocks, TPB>>>((const float4*)x, (float4*)y);
    }
    int done = full_blocks * elems_per_block;
    int rem = n - done;
    if (rem > 0) {
        int blocks = (rem + 255) / 256;
        k1_tail<<<blocks, 256>>>(x, y, done, n);
    }
}